// round 2
// baseline (speedup 1.0000x reference)
#include <cuda_runtime.h>
#include <cuda_bf16.h>
#include <cstdint>
#include <cstddef>

#define B_   512
#define T_   2048
#define C_   8
#define NP   800          // C*M pairs
#define TPB  512
#define NBLK 128          // B_/4, 4 batches per block

#define L2E     1.4426950408889634f
#define TWO_L2E 2.8853900817779268f
#define SQ_L2E  1.2011224087864498f

// ---- shared layout (float offsets) ----
#define OFF_SQ   0        // float4 Sq[4][800]   : S quads transposed, *2*log2e (12800 f)
#define OFF_AT   12800    // float  at[16][804]  : A transposed, padded         (12864 f)
#define OFF_UK   25664    // float2 uk[800]      : (U*sqrt(l2e), l2e*|S|^2)     ( 1600 f)
#define OFF_W    27264    // float  w[4][804]                                    ( 3216 f)
#define OFF_RED  30480    // float  red[4][16][16]                               ( 1024 f)
#define OFF_ST   31504    // float  st[4][20]    : [0..15]=state, [16]=ss        (   80 f)
#define OFF_GATE 31584    // float  gate[2][4][8]                                (   64 f)
#define OFF_XB   31648    // float  xb[2][4]                                     (    8 f)
#define SMEM_FLOATS 31656
#define SMEM_BYTES  (SMEM_FLOATS * 4)

// Precomputed softmax gates, gate[b][t][c]
__device__ float g_gate[(size_t)B_ * T_ * C_];

__device__ __forceinline__ float ex2f(float a)
{
    float r;
    asm("ex2.approx.ftz.f32 %0, %1;" : "=f"(r) : "f"(a));
    return r;
}

// ---------------------------------------------------------------------------
// Kernel 1: gate[b,t,:] = softmax(relu(x*W1+b1) @ W2 + b2). One thread per (b,t).
// ---------------------------------------------------------------------------
__global__ void gate_kernel(const float* __restrict__ x,
                            const float* __restrict__ W1,
                            const float* __restrict__ b1,
                            const float* __restrict__ W2,
                            const float* __restrict__ b2)
{
    int idx = blockIdx.x * blockDim.x + threadIdx.x;
    if (idx >= B_ * T_) return;
    float xv = x[idx];

    float lg[8];
#pragma unroll
    for (int c = 0; c < 8; c++) lg[c] = __ldg(&b2[c]);
#pragma unroll
    for (int jj = 0; jj < 16; jj++) {
        float h = fmaxf(fmaf(xv, __ldg(&W1[jj]), __ldg(&b1[jj])), 0.0f);
#pragma unroll
        for (int c = 0; c < 8; c++)
            lg[c] = fmaf(h, __ldg(&W2[jj * 8 + c]), lg[c]);
    }
    float m = lg[0];
#pragma unroll
    for (int c = 1; c < 8; c++) m = fmaxf(m, lg[c]);
    float e[8], ssum = 0.0f;
#pragma unroll
    for (int c = 0; c < 8; c++) { e[c] = __expf(lg[c] - m); ssum += e[c]; }
    float inv = 1.0f / ssum;
#pragma unroll
    for (int c = 0; c < 8; c++) g_gate[(size_t)idx * 8 + c] = e[c] * inv;
}

// ---------------------------------------------------------------------------
// Kernel 2: recurrent scan. 128 blocks x 512 threads, 4 batches per block.
// ---------------------------------------------------------------------------
__global__ void __launch_bounds__(TPB, 1)
scan_kernel(const float* __restrict__ x,
            const float* __restrict__ S,
            const float* __restrict__ U,
            const float* __restrict__ A,
            float* __restrict__ out)
{
    extern __shared__ float sm[];
    const int tid = threadIdx.x;
    const int b0  = blockIdx.x * 4;

    // ---------------- stage S', A^T, (U', k) ----------------
    for (int idx = tid; idx < NP * 16; idx += TPB) {
        int p = idx >> 4, k = idx & 15;
        sm[OFF_SQ + (k >> 2) * 3200 + (p << 2) + (k & 3)] = TWO_L2E * S[idx];
        sm[OFF_AT + k * 804 + p] = A[idx];
    }
    for (int p = tid; p < NP; p += TPB) {
        float acc = 0.0f;
#pragma unroll
        for (int k = 0; k < 16; k++) { float v = S[p * 16 + k]; acc = fmaf(v, v, acc); }
        sm[OFF_UK + 2 * p]     = SQ_L2E * U[p];
        sm[OFF_UK + 2 * p + 1] = L2E * acc;
    }
    if (tid < 32) {
        int bb = tid >> 3, cc = tid & 7;
        sm[OFF_GATE + bb * 8 + cc] = g_gate[((size_t)(b0 + bb) * T_) * C_ + cc];
        if (tid < 4) sm[OFF_XB + tid] = SQ_L2E * x[(size_t)(b0 + tid) * T_];
    }
    __syncthreads();

    const int b    = tid & 3;    // phase A batch
    const int pp   = tid >> 2;   // phase A pair lane (0..127)
    const int n    = tid & 15;   // phase B output dim
    const int j    = tid >> 4;   // phase B chunk (0..31)
    const int lane = tid & 31;
    const int wrp  = tid >> 5;

    // per-batch state kept in registers (4 quads), ss = l2e*|s|^2, xs = sqrt(l2e)*x_t
    float4 r0 = make_float4(0.f, 0.f, 0.f, 0.f), r1 = r0, r2 = r0, r3 = r0;
    float ss = 0.0f;
    float xs = sm[OFF_XB + b];

    const float4* Sq4 = (const float4*)(sm + OFF_SQ);
    const float4* At4 = (const float4*)(sm + OFF_AT + n * 804);
    const float4* W4  = (const float4*)(sm + OFF_W);

    for (int t = 0; t < T_; t++) {
        const int par = t & 1;

        // issue next-step gate/x loads (consumed at end of step)
        float gpre = 0.f, xpre = 0.f;
        const bool pf = (tid < 32) && (t + 1 < T_);
        if (pf) {
            gpre = g_gate[((size_t)(b0 + (tid >> 3)) * T_ + (t + 1)) * C_ + (tid & 7)];
            if (tid < 4) xpre = SQ_L2E * x[(size_t)(b0 + tid) * T_ + (t + 1)];
        }

        // ---------------- phase A: w[b][p] = gate * exp2(...) ----------------
        {
            const float* gsh  = sm + OFF_GATE + par * 32 + b * 8;
            float*       wrow = sm + OFF_W + b * 804;
            for (int p = pp; p < NP; p += 128) {
                float4 q0 = Sq4[p];
                float4 q1 = Sq4[800 + p];
                float4 q2 = Sq4[1600 + p];
                float4 q3 = Sq4[2400 + p];
                float d0 = fmaf(q0.x, r0.x, fmaf(q0.y, r0.y, fmaf(q0.z, r0.z, q0.w * r0.w)));
                float d1 = fmaf(q1.x, r1.x, fmaf(q1.y, r1.y, fmaf(q1.z, r1.z, q1.w * r1.w)));
                float d2 = fmaf(q2.x, r2.x, fmaf(q2.y, r2.y, fmaf(q2.z, r2.z, q2.w * r2.w)));
                float d3 = fmaf(q3.x, r3.x, fmaf(q3.y, r3.y, fmaf(q3.z, r3.z, q3.w * r3.w)));
                float dot = (d0 + d1) + (d2 + d3);
                float2 uk = *(const float2*)(sm + OFF_UK + 2 * p);
                float du = xs - uk.x;
                float e  = (dot - ss) - fmaf(du, du, uk.y);
                unsigned c = (unsigned)p / 100u;
                wrow[p] = gsh[c] * ex2f(e);
            }
        }
        __syncthreads();

        // ---------------- phase B: s_new[b][n] = sum_p w[b][p]*A[p][n] -------
        float a0 = 0.f, a1 = 0.f, a2 = 0.f, a3 = 0.f;
        for (int p4 = j; p4 < 200; p4 += 32) {
            float4 av = At4[p4];
            float4 w0 = W4[p4];
            float4 w1 = W4[201 + p4];
            float4 w2 = W4[402 + p4];
            float4 w3 = W4[603 + p4];
            a0 = fmaf(av.x, w0.x, a0); a0 = fmaf(av.y, w0.y, a0);
            a0 = fmaf(av.z, w0.z, a0); a0 = fmaf(av.w, w0.w, a0);
            a1 = fmaf(av.x, w1.x, a1); a1 = fmaf(av.y, w1.y, a1);
            a1 = fmaf(av.z, w1.z, a1); a1 = fmaf(av.w, w1.w, a1);
            a2 = fmaf(av.x, w2.x, a2); a2 = fmaf(av.y, w2.y, a2);
            a2 = fmaf(av.z, w2.z, a2); a2 = fmaf(av.w, w2.w, a2);
            a3 = fmaf(av.x, w3.x, a3); a3 = fmaf(av.y, w3.y, a3);
            a3 = fmaf(av.z, w3.z, a3); a3 = fmaf(av.w, w3.w, a3);
        }
        // pair-combine j and j^1 within the warp, then park per-warp partials
        a0 += __shfl_xor_sync(0xffffffffu, a0, 16);
        a1 += __shfl_xor_sync(0xffffffffu, a1, 16);
        a2 += __shfl_xor_sync(0xffffffffu, a2, 16);
        a3 += __shfl_xor_sync(0xffffffffu, a3, 16);
        if (lane < 16) {
            sm[OFF_RED +       wrp * 16 + lane] = a0;
            sm[OFF_RED + 256 + wrp * 16 + lane] = a1;
            sm[OFF_RED + 512 + wrp * 16 + lane] = a2;
            sm[OFF_RED + 768 + wrp * 16 + lane] = a3;
        }
        __syncthreads();

        // ---------------- final reduce, ss, output ----------------
        if (tid < 64) {
            const int bb = tid >> 4, nn = tid & 15;
            float v = 0.0f;
#pragma unroll
            for (int w = 0; w < 16; w++) v += sm[OFF_RED + bb * 256 + w * 16 + nn];
            float vv = v * v;
            vv += __shfl_xor_sync(0xffffffffu, vv, 1);
            vv += __shfl_xor_sync(0xffffffffu, vv, 2);
            vv += __shfl_xor_sync(0xffffffffu, vv, 4);
            vv += __shfl_xor_sync(0xffffffffu, vv, 8);
            sm[OFF_ST + bb * 20 + nn] = v;
            if (nn == 0)  sm[OFF_ST + bb * 20 + 16] = L2E * vv;
            if (nn == 15) out[(size_t)(b0 + bb) * T_ + t] = v;
        }
        // commit prefetched gate/x for t+1 (other parity buffer)
        if (pf) {
            sm[OFF_GATE + (par ^ 1) * 32 + (tid >> 3) * 8 + (tid & 7)] = gpre;
            if (tid < 4) sm[OFF_XB + (par ^ 1) * 4 + tid] = xpre;
        }
        __syncthreads();

        // reload state for next step
        const float4* st4 = (const float4*)(sm + OFF_ST + b * 20);
        r0 = st4[0]; r1 = st4[1]; r2 = st4[2]; r3 = st4[3];
        ss = sm[OFF_ST + b * 20 + 16];
        xs = sm[OFF_XB + (par ^ 1) * 4 + b];
    }
}

// ---------------------------------------------------------------------------
extern "C" void kernel_launch(void* const* d_in, const int* in_sizes, int n_in,
                              void* d_out, int out_size)
{
    const float* x  = (const float*)d_in[0];
    const float* S  = (const float*)d_in[1];
    const float* U  = (const float*)d_in[2];
    const float* A  = (const float*)d_in[3];
    const float* W1 = (const float*)d_in[4];
    const float* b1 = (const float*)d_in[5];
    const float* W2 = (const float*)d_in[6];
    const float* b2 = (const float*)d_in[7];
    float* out = (float*)d_out;

    cudaFuncSetAttribute(scan_kernel,
                         cudaFuncAttributeMaxDynamicSharedMemorySize, SMEM_BYTES);

    gate_kernel<<<(B_ * T_ + 255) / 256, 256>>>(x, W1, b1, W2, b2);
    scan_kernel<<<NBLK, TPB, SMEM_BYTES>>>(x, S, U, A, out);
}

// round 3
// speedup vs baseline: 1.1412x; 1.1412x over previous
#include <cuda_runtime.h>
#include <cuda_bf16.h>
#include <cstdint>
#include <cstddef>

#define B_   512
#define T_   2048
#define NP   800          // C*M pairs
#define TPB  512
#define NBLK 128          // B_/4, 4 batches per block

#define L2E     1.4426950408889634f
#define TWO_L2E 2.8853900817779268f
#define SQ_L2E  1.2011224087864498f

// ---- shared layout (float offsets) ----
#define OFF_SQ   0        // float4 Sq[4][800] : S quads transposed, *2*log2e (12800 f)
#define OFF_AT   12800    // float  at[16][804]: A transposed, padded         (12864 f)
#define OFF_UK   25664    // float2 uk[800]    : (U*sqrt(l2e), l2e*|S|^2)     ( 1600 f)
#define OFF_W    27264    // float  w[4][808]  : stride 808 -> conflict-free  ( 3232 f)
#define OFF_RED  30496    // float  red[4][16][16]                            ( 1024 f)
#define OFF_ST   31520    // float  st[4][20]                                 (   80 f)
#define OFF_GATE 31600    // float  gate[2][4][8]                             (   64 f)
#define OFF_XB   31664    // float  xb[2][4]                                  (    8 f)
#define SMEM_FLOATS 31672
#define SMEM_BYTES  (SMEM_FLOATS * 4)

typedef unsigned long long u64;

__device__ float g_gate[(size_t)B_ * T_ * 8];

__device__ __forceinline__ float ex2f(float a)
{
    float r;
    asm("ex2.approx.ftz.f32 %0, %1;" : "=f"(r) : "f"(a));
    return r;
}
__device__ __forceinline__ u64 fma2(u64 b, u64 c, u64 a)   // b*c + a
{
    u64 d;
    asm("fma.rn.f32x2 %0, %1, %2, %3;" : "=l"(d) : "l"(b), "l"(c), "l"(a));
    return d;
}
__device__ __forceinline__ u64 mul2(u64 a, u64 b)
{
    u64 d;
    asm("mul.rn.f32x2 %0, %1, %2;" : "=l"(d) : "l"(a), "l"(b));
    return d;
}
__device__ __forceinline__ float2 upk(u64 a)
{
    float2 f;
    asm("mov.b64 {%0, %1}, %2;" : "=f"(f.x), "=f"(f.y) : "l"(a));
    return f;
}

// ---------------------------------------------------------------------------
// Kernel 1: gate[b,t,:] = softmax(relu(x*W1+b1) @ W2 + b2). One thread per (b,t).
// ---------------------------------------------------------------------------
__global__ void gate_kernel(const float* __restrict__ x,
                            const float* __restrict__ W1,
                            const float* __restrict__ b1,
                            const float* __restrict__ W2,
                            const float* __restrict__ b2)
{
    int idx = blockIdx.x * blockDim.x + threadIdx.x;
    if (idx >= B_ * T_) return;
    float xv = x[idx];

    float lg[8];
#pragma unroll
    for (int c = 0; c < 8; c++) lg[c] = __ldg(&b2[c]);
#pragma unroll
    for (int jj = 0; jj < 16; jj++) {
        float h = fmaxf(fmaf(xv, __ldg(&W1[jj]), __ldg(&b1[jj])), 0.0f);
#pragma unroll
        for (int c = 0; c < 8; c++)
            lg[c] = fmaf(h, __ldg(&W2[jj * 8 + c]), lg[c]);
    }
    float m = lg[0];
#pragma unroll
    for (int c = 1; c < 8; c++) m = fmaxf(m, lg[c]);
    float e[8], ssum = 0.0f;
#pragma unroll
    for (int c = 0; c < 8; c++) { e[c] = __expf(lg[c] - m); ssum += e[c]; }
    float inv = 1.0f / ssum;
#pragma unroll
    for (int c = 0; c < 8; c++) g_gate[(size_t)idx * 8 + c] = e[c] * inv;
}

// ---------------------------------------------------------------------------
// Kernel 2: recurrent scan. 128 blocks x 512 threads, 4 batches per block.
// ---------------------------------------------------------------------------
__global__ void __launch_bounds__(TPB, 1)
scan_kernel(const float* __restrict__ x,
            const float* __restrict__ S,
            const float* __restrict__ U,
            const float* __restrict__ A,
            float* __restrict__ out)
{
    extern __shared__ float sm[];
    const int tid = threadIdx.x;
    const int b0  = blockIdx.x * 4;

    // ---------------- stage S', A^T, (U', k) ----------------
    for (int idx = tid; idx < NP * 16; idx += TPB) {
        int p = idx >> 4, k = idx & 15;
        sm[OFF_SQ + (k >> 2) * 3200 + (p << 2) + (k & 3)] = TWO_L2E * S[idx];
        sm[OFF_AT + k * 804 + p] = A[idx];
    }
    for (int p = tid; p < NP; p += TPB) {
        float acc = 0.0f;
#pragma unroll
        for (int k = 0; k < 16; k++) { float v = S[p * 16 + k]; acc = fmaf(v, v, acc); }
        sm[OFF_UK + 2 * p]     = SQ_L2E * U[p];
        sm[OFF_UK + 2 * p + 1] = L2E * acc;
    }
    if (tid < 32) {
        sm[OFF_GATE + tid] = g_gate[((size_t)(b0 + (tid >> 3)) * T_) * 8 + (tid & 7)];
        if (tid < 4) sm[OFF_XB + tid] = SQ_L2E * x[(size_t)(b0 + tid) * T_];
    }
    __syncthreads();

    const int b    = tid & 3;    // phase A batch
    const int pp   = tid >> 2;   // phase A pair lane (0..127)
    const int nn   = tid & 15;   // phase B output dim
    const int j    = tid >> 4;   // phase B chunk lane (0..31)
    const int lane = tid & 31;
    const int wrp  = tid >> 5;

    // precomputed cell index (p/100) for each unrolled phase-A iteration
    int cA[7];
#pragma unroll
    for (int i = 0; i < 6; i++) cA[i] = (unsigned)(pp + 128 * i) / 100u;
    cA[6] = (unsigned)(672 + pp) / 100u;       // valid only when pp >= 96

    // packed state (8 x f32x2), ss = l2e*|s|^2, xs = sqrt(l2e)*x_t
    u64 s0 = 0, s1 = 0, s2 = 0, s3 = 0, s4 = 0, s5 = 0, s6 = 0, s7 = 0;
    float ss = 0.0f;
    float xs = sm[OFF_XB + b];

    const ulonglong2* Sq2 = (const ulonglong2*)(sm + OFF_SQ);
    const ulonglong2* At2 = (const ulonglong2*)(sm + OFF_AT + nn * 804);
    const ulonglong2* Wb2 = (const ulonglong2*)(sm + OFF_W);

    for (int t = 0; t < T_; t++) {
        const int par = t & 1;

        // issue next-step gate/x loads (committed after bar1, consumed at step end)
        float gpre = 0.f, xpre = 0.f;
        const bool pf = (tid < 32) && (t + 1 < T_);
        if (pf) {
            gpre = g_gate[((size_t)(b0 + (tid >> 3)) * T_ + (t + 1)) * 8 + (tid & 7)];
            if (tid < 4) xpre = SQ_L2E * x[(size_t)(b0 + tid) * T_ + (t + 1)];
        }

        // ---------------- phase A: w[b][p] = gate * exp2(...) ----------------
        {
            const float* gsh  = sm + OFF_GATE + par * 32 + b * 8;
            float*       wrow = sm + OFF_W + b * 808;

            auto pairA = [&](int p, int ci) {
                ulonglong2 q0 = Sq2[p];
                ulonglong2 q1 = Sq2[800 + p];
                ulonglong2 q2 = Sq2[1600 + p];
                ulonglong2 q3 = Sq2[2400 + p];
                u64 da = mul2(q0.x, s0);
                da = fma2(q0.y, s1, da);
                da = fma2(q1.x, s2, da);
                da = fma2(q1.y, s3, da);
                u64 db = mul2(q2.x, s4);
                db = fma2(q2.y, s5, db);
                db = fma2(q3.x, s6, db);
                db = fma2(q3.y, s7, db);
                float2 fa = upk(da), fb = upk(db);
                float dot = (fa.x + fa.y) + (fb.x + fb.y);
                float2 uk = *(const float2*)(sm + OFF_UK + 2 * p);
                float du = xs - uk.x;
                float e  = (dot - ss) - fmaf(du, du, uk.y);
                wrow[p] = gsh[ci] * ex2f(e);
            };
#pragma unroll
            for (int i = 0; i < 6; i++) pairA(pp + 128 * i, cA[i]);
            if (pp >= 96) pairA(672 + pp, cA[6]);   // tail pairs 768..799 on warps 12-15
        }
        __syncthreads();                             // bar 1

        // commit prefetched gate/x for t+1 (off the critical tail)
        if (pf) {
            sm[OFF_GATE + (par ^ 1) * 32 + tid] = gpre;
            if (tid < 4) sm[OFF_XB + (par ^ 1) * 4 + tid] = xpre;
        }

        // ---------------- phase B: s_new[b][n] = sum_p w[b][p]*A[p][n] -------
        u64 c0 = 0, c1 = 0, c2 = 0, c3 = 0;
        auto chunkB = [&](int p4) {
            ulonglong2 av = At2[p4];
            ulonglong2 w0 = Wb2[p4];
            ulonglong2 w1 = Wb2[202 + p4];
            ulonglong2 w2 = Wb2[404 + p4];
            ulonglong2 w3 = Wb2[606 + p4];
            c0 = fma2(av.x, w0.x, c0); c0 = fma2(av.y, w0.y, c0);
            c1 = fma2(av.x, w1.x, c1); c1 = fma2(av.y, w1.y, c1);
            c2 = fma2(av.x, w2.x, c2); c2 = fma2(av.y, w2.y, c2);
            c3 = fma2(av.x, w3.x, c3); c3 = fma2(av.y, w3.y, c3);
        };
#pragma unroll
        for (int i = 0; i < 6; i++) chunkB(j + 32 * i);
        if (j >= 24) chunkB(168 + j);               // tail chunks 192..199 on warps 12-15

        float2 f0 = upk(c0), f1 = upk(c1), f2 = upk(c2), f3 = upk(c3);
        float a0 = f0.x + f0.y, a1 = f1.x + f1.y, a2 = f2.x + f2.y, a3 = f3.x + f3.y;
        a0 += __shfl_xor_sync(0xffffffffu, a0, 16);
        a1 += __shfl_xor_sync(0xffffffffu, a1, 16);
        a2 += __shfl_xor_sync(0xffffffffu, a2, 16);
        a3 += __shfl_xor_sync(0xffffffffu, a3, 16);
        if (lane < 16) {
            sm[OFF_RED +       wrp * 16 + lane] = a0;
            sm[OFF_RED + 256 + wrp * 16 + lane] = a1;
            sm[OFF_RED + 512 + wrp * 16 + lane] = a2;
            sm[OFF_RED + 768 + wrp * 16 + lane] = a3;
        }
        __syncthreads();                             // bar 2

        // ---------------- final reduce + output ----------------
        if (tid < 64) {
            const int bb = tid >> 4, n2 = tid & 15;
            const float* r = sm + OFF_RED + bb * 256 + n2;
            float v = 0.0f;
#pragma unroll
            for (int w = 0; w < 16; w++) v += r[w * 16];
            sm[OFF_ST + bb * 20 + n2] = v;
            if (n2 == 15) out[(size_t)(b0 + bb) * T_ + t] = v;
        }
        __syncthreads();                             // bar 3

        // reload packed state; recompute ss locally (no serial shuffle chain)
        {
            const ulonglong2* st2 = (const ulonglong2*)(sm + OFF_ST + b * 20);
            ulonglong2 u0 = st2[0], u1 = st2[1], u2 = st2[2], u3 = st2[3];
            s0 = u0.x; s1 = u0.y; s2 = u1.x; s3 = u1.y;
            s4 = u2.x; s5 = u2.y; s6 = u3.x; s7 = u3.y;
            u64 acc = mul2(s0, s0);
            acc = fma2(s1, s1, acc);
            acc = fma2(s2, s2, acc);
            acc = fma2(s3, s3, acc);
            acc = fma2(s4, s4, acc);
            acc = fma2(s5, s5, acc);
            acc = fma2(s6, s6, acc);
            acc = fma2(s7, s7, acc);
            float2 fs = upk(acc);
            ss = L2E * (fs.x + fs.y);
            xs = sm[OFF_XB + (par ^ 1) * 4 + b];
        }
    }
}

// ---------------------------------------------------------------------------
extern "C" void kernel_launch(void* const* d_in, const int* in_sizes, int n_in,
                              void* d_out, int out_size)
{
    const float* x  = (const float*)d_in[0];
    const float* S  = (const float*)d_in[1];
    const float* U  = (const float*)d_in[2];
    const float* A  = (const float*)d_in[3];
    const float* W1 = (const float*)d_in[4];
    const float* b1 = (const float*)d_in[5];
    const float* W2 = (const float*)d_in[6];
    const float* b2 = (const float*)d_in[7];
    float* out = (float*)d_out;

    cudaFuncSetAttribute(scan_kernel,
                         cudaFuncAttributeMaxDynamicSharedMemorySize, SMEM_BYTES);

    gate_kernel<<<(B_ * T_ + 255) / 256, 256>>>(x, W1, b1, W2, b2);
    scan_kernel<<<NBLK, TPB, SMEM_BYTES>>>(x, S, U, A, out);
}